// round 4
// baseline (speedup 1.0000x reference)
#include <cuda_runtime.h>
#include <math.h>

#define T_LEN  1024
#define D_DIM  256
#define K_CH   4
#define NCHUNK 128
#define L_CH   8          // T_LEN / NCHUNK
#define NROUND 7          // log2(NCHUNK)

// Constants passed by value (computed in double on host; deterministic).
struct HippoConsts {
    float Ab[16];              // Abar (row-major 4x4)
    float Bb[4];               // Bbar
    float Pk[NROUND][16];      // Abar^(L_CH * 2^r), r = 0..6
};

// Static scratch (no allocs allowed). B <= 8 supported.
__device__ float4 g_e[8 * NCHUNK * D_DIM];      // chunk end-states
__device__ float4 g_start[8 * NCHUNK * D_DIM];  // chunk start-states

// ---- software grid barrier (sense reversal; state self-resets across replays) ----
__device__ unsigned g_cnt = 0;
__device__ volatile unsigned g_sense = 0;

__device__ __forceinline__ void grid_barrier() {
    __syncthreads();
    if (threadIdx.x == 0) {
        const unsigned total = gridDim.x * gridDim.y;
        __threadfence();                    // publish this block's global writes
        unsigned s = g_sense;               // read sense BEFORE arriving
        if (atomicAdd(&g_cnt, 1u) == total - 1u) {
            g_cnt = 0;
            __threadfence();
            g_sense = s + 1u;               // release
        } else {
            while (g_sense == s) __nanosleep(32);
        }
        __threadfence();                    // acquire
    }
    __syncthreads();
}

// One recurrence step: x = Ab*x + Bb*hv
#define RSTEP(hv)                                                              \
    {                                                                          \
        float y0 = fmaf(c.Ab[0],  x0, fmaf(c.Ab[1],  x1,                       \
                   fmaf(c.Ab[2],  x2, fmaf(c.Ab[3],  x3, c.Bb[0] * (hv)))));   \
        float y1 = fmaf(c.Ab[4],  x0, fmaf(c.Ab[5],  x1,                       \
                   fmaf(c.Ab[6],  x2, fmaf(c.Ab[7],  x3, c.Bb[1] * (hv)))));   \
        float y2 = fmaf(c.Ab[8],  x0, fmaf(c.Ab[9],  x1,                       \
                   fmaf(c.Ab[10], x2, fmaf(c.Ab[11], x3, c.Bb[2] * (hv)))));   \
        float y3 = fmaf(c.Ab[12], x0, fmaf(c.Ab[13], x1,                       \
                   fmaf(c.Ab[14], x2, fmaf(c.Ab[15], x3, c.Bb[3] * (hv)))));   \
        x0 = y0; x1 = y1; x2 = y2; x3 = y3;                                    \
    }

// v = M*p + v  (4x4 matvec-accumulate on float4)
__device__ __forceinline__ float4 mvacc(const float* M, float4 p, float4 v) {
    float4 r;
    r.x = fmaf(M[0],  p.x, fmaf(M[1],  p.y, fmaf(M[2],  p.z, fmaf(M[3],  p.w, v.x))));
    r.y = fmaf(M[4],  p.x, fmaf(M[5],  p.y, fmaf(M[6],  p.z, fmaf(M[7],  p.w, v.y))));
    r.z = fmaf(M[8],  p.x, fmaf(M[9],  p.y, fmaf(M[10], p.z, fmaf(M[11], p.w, v.z))));
    r.w = fmaf(M[12], p.x, fmaf(M[13], p.y, fmaf(M[14], p.z, fmaf(M[15], p.w, v.w))));
    return r;
}

__global__ __launch_bounds__(256, 2)
void hippo_fused(const float* __restrict__ h, float* __restrict__ out, HippoConsts c) {
    __shared__ float4 s[256];
    const int tid = threadIdx.x;
    const int b   = blockIdx.y;

    // ================= Phase 1: chunk-local recurrence (block = chunk j) =========
    {
        const int j = blockIdx.x;
        const int d = tid;
        const float* hp = h + ((size_t)(b * T_LEN + j * L_CH)) * D_DIM + d;
        float x0 = 0.f, x1 = 0.f, x2 = 0.f, x3 = 0.f;
        #pragma unroll
        for (int t = 0; t < L_CH; t++) {
            float hv = __ldg(hp + (size_t)t * D_DIM);
            RSTEP(hv);
        }
        g_e[((size_t)b * NCHUNK + j) * D_DIM + d] = make_float4(x0, x1, x2, x3);
    }

    grid_barrier();

    // ================= Phase 2: Kogge-Stone scan (block = d-pair) ================
    {
        const int j  = tid & (NCHUNK - 1);
        const int dd = tid >> 7;
        const int d  = blockIdx.x * 2 + dd;
        const size_t base = (size_t)b * NCHUNK * D_DIM + d;

        float4 v = g_e[base + (size_t)j * D_DIM];
        s[tid] = v;
        __syncthreads();

        #pragma unroll
        for (int r = 0; r < NROUND; r++) {
            const int off = 1 << r;
            float4 prev = make_float4(0.f, 0.f, 0.f, 0.f);
            const bool pred = (j >= off);
            if (pred) prev = s[tid - off];
            __syncthreads();
            if (pred) v = mvacc(c.Pk[r], prev, v);   // v += P^(2^r) * prev
            s[tid] = v;
            __syncthreads();
        }

        float4 st = make_float4(0.f, 0.f, 0.f, 0.f);   // exclusive prefix
        if (j > 0) st = s[tid - 1];
        g_start[base + (size_t)j * D_DIM] = st;
    }

    grid_barrier();

    // ================= Phase 3: replay + write (block = chunk j) =================
    {
        const int j = blockIdx.x;
        const int d = tid;

        float4 xs = g_start[((size_t)b * NCHUNK + j) * D_DIM + d];
        float x0 = xs.x, x1 = xs.y, x2 = xs.z, x3 = xs.w;

        const float* hp = h + ((size_t)(b * T_LEN + j * L_CH)) * D_DIM + d;
        float* op = out + ((size_t)(b * T_LEN + j * L_CH)) * K_CH * D_DIM + d;

        #pragma unroll
        for (int t = 0; t < L_CH; t++) {
            float hv = __ldg(hp + (size_t)t * D_DIM);
            RSTEP(hv);
            op[0]         = x0;
            op[D_DIM]     = x1;
            op[2 * D_DIM] = x2;
            op[3 * D_DIM] = x3;
            op += (size_t)K_CH * D_DIM;
        }
    }
}

// ---------------- host-side constant construction (double precision) ----------------

static void inv4x4(const double Min[4][4], double Mout[4][4]) {
    double a[4][8];
    for (int i = 0; i < 4; i++)
        for (int jj = 0; jj < 8; jj++)
            a[i][jj] = (jj < 4) ? Min[i][jj] : (jj - 4 == i ? 1.0 : 0.0);
    for (int col = 0; col < 4; col++) {
        int p = col;
        for (int rr = col + 1; rr < 4; rr++)
            if (fabs(a[rr][col]) > fabs(a[p][col])) p = rr;
        if (p != col)
            for (int jj = 0; jj < 8; jj++) { double t = a[col][jj]; a[col][jj] = a[p][jj]; a[p][jj] = t; }
        double piv = a[col][col];
        for (int jj = 0; jj < 8; jj++) a[col][jj] /= piv;
        for (int rr = 0; rr < 4; rr++) {
            if (rr == col) continue;
            double f = a[rr][col];
            for (int jj = 0; jj < 8; jj++) a[rr][jj] -= f * a[col][jj];
        }
    }
    for (int i = 0; i < 4; i++)
        for (int jj = 0; jj < 4; jj++)
            Mout[i][jj] = a[i][jj + 4];
}

static void matmul4(const double A[4][4], const double B[4][4], double C[4][4]) {
    for (int i = 0; i < 4; i++)
        for (int jj = 0; jj < 4; jj++) {
            double s = 0.0;
            for (int k = 0; k < 4; k++) s += A[i][k] * B[k][jj];
            C[i][jj] = s;
        }
}

extern "C" void kernel_launch(void* const* d_in, const int* in_sizes, int n_in,
                              void* d_out, int out_size) {
    const float* h;
    int sz0 = in_sizes[0], sz1 = in_sizes[1];
    if (sz0 > sz1) h = (const float*)d_in[0];
    else           h = (const float*)d_in[1];
    int hsz = (sz0 > sz1) ? sz0 : sz1;
    int B = hsz / (T_LEN * D_DIM);

    // --- HiPPO-LegT constants (matches reference _make_hippo_legt + bilinear) ---
    const double theta = 200.0;
    const double dt = 1.0 / theta;
    double A[4][4], Bv[4], Pn[4];
    for (int i = 0; i < 4; i++) Pn[i] = sqrt(2.0 * i + 1.0);
    for (int i = 0; i < 4; i++) {
        Bv[i] = Pn[i];
        for (int jj = 0; jj < 4; jj++) {
            double sg = 1.0;
            if (jj > i && ((jj - i) & 1)) sg = -1.0;   // (-1)^(j-i) upper triangle
            A[i][jj] = -Pn[i] * Pn[jj] * sg;
        }
    }
    double ImA[4][4], IpA[4][4], Inv[4][4], Abar[4][4];
    for (int i = 0; i < 4; i++)
        for (int jj = 0; jj < 4; jj++) {
            double eye = (i == jj) ? 1.0 : 0.0;
            ImA[i][jj] = eye - 0.5 * dt * A[i][jj];
            IpA[i][jj] = eye + 0.5 * dt * A[i][jj];
        }
    inv4x4(ImA, Inv);
    matmul4(Inv, IpA, Abar);
    double Bbar[4];
    for (int i = 0; i < 4; i++) {
        double sacc = 0.0;
        for (int jj = 0; jj < 4; jj++) sacc += Inv[i][jj] * Bv[jj] * dt;
        Bbar[i] = sacc;
    }

    // Pk[r] = Abar^(L_CH * 2^r)
    double Pw[NROUND][4][4], Tmp[4][4], Cur[4][4];
    for (int i = 0; i < 4; i++)
        for (int jj = 0; jj < 4; jj++) Cur[i][jj] = (i == jj) ? 1.0 : 0.0;
    for (int m = 0; m < L_CH; m++) {
        matmul4(Cur, Abar, Tmp);
        for (int i = 0; i < 4; i++)
            for (int jj = 0; jj < 4; jj++) Cur[i][jj] = Tmp[i][jj];
    }
    for (int i = 0; i < 4; i++)
        for (int jj = 0; jj < 4; jj++) Pw[0][i][jj] = Cur[i][jj];
    for (int r = 1; r < NROUND; r++) {
        matmul4(Pw[r - 1], Pw[r - 1], Tmp);
        for (int i = 0; i < 4; i++)
            for (int jj = 0; jj < 4; jj++) Pw[r][i][jj] = Tmp[i][jj];
    }

    HippoConsts c;
    for (int i = 0; i < 4; i++) {
        c.Bb[i] = (float)Bbar[i];
        for (int jj = 0; jj < 4; jj++)
            c.Ab[i * 4 + jj] = (float)Abar[i][jj];
    }
    for (int r = 0; r < NROUND; r++)
        for (int i = 0; i < 16; i++)
            c.Pk[r][i] = (float)Pw[r][i / 4][i % 4];

    dim3 grid(NCHUNK, B);   // 128 x B = 256 blocks; all co-resident (<= 296 slots)
    hippo_fused<<<grid, D_DIM>>>(h, (float*)d_out, c);
}

// round 5
// speedup vs baseline: 1.3642x; 1.3642x over previous
#include <cuda_runtime.h>
#include <math.h>

#define T_LEN  1024
#define D_DIM  256
#define K_CH   4
#define NCHUNK 128
#define L_CH   8          // T_LEN / NCHUNK
#define NROUND 7          // log2(NCHUNK)

// Constants passed by value (computed in double on host; deterministic).
struct HippoConsts {
    float Ab[16];              // Abar (row-major 4x4)
    float Bb[4];               // Bbar
    float Pk[NROUND][16];      // Abar^(L_CH * 2^r), r = 0..6
};

// Static scratch (no allocs allowed). B <= 8 supported.
__device__ float4 g_eT[8 * D_DIM * NCHUNK];     // end-states, TRANSPOSED [b][d][j]
__device__ float4 g_start[8 * NCHUNK * D_DIM];  // start-states, [b][j][d]

// One recurrence step: x = Ab*x + Bb*hv
#define RSTEP(hv)                                                              \
    {                                                                          \
        float y0 = fmaf(c.Ab[0],  x0, fmaf(c.Ab[1],  x1,                       \
                   fmaf(c.Ab[2],  x2, fmaf(c.Ab[3],  x3, c.Bb[0] * (hv)))));   \
        float y1 = fmaf(c.Ab[4],  x0, fmaf(c.Ab[5],  x1,                       \
                   fmaf(c.Ab[6],  x2, fmaf(c.Ab[7],  x3, c.Bb[1] * (hv)))));   \
        float y2 = fmaf(c.Ab[8],  x0, fmaf(c.Ab[9],  x1,                       \
                   fmaf(c.Ab[10], x2, fmaf(c.Ab[11], x3, c.Bb[2] * (hv)))));   \
        float y3 = fmaf(c.Ab[12], x0, fmaf(c.Ab[13], x1,                       \
                   fmaf(c.Ab[14], x2, fmaf(c.Ab[15], x3, c.Bb[3] * (hv)))));   \
        x0 = y0; x1 = y1; x2 = y2; x3 = y3;                                    \
    }

// v = M*p + v  (4x4 matvec-accumulate on float4)
__device__ __forceinline__ float4 mvacc(const float* M, float4 p, float4 v) {
    float4 r;
    r.x = fmaf(M[0],  p.x, fmaf(M[1],  p.y, fmaf(M[2],  p.z, fmaf(M[3],  p.w, v.x))));
    r.y = fmaf(M[4],  p.x, fmaf(M[5],  p.y, fmaf(M[6],  p.z, fmaf(M[7],  p.w, v.y))));
    r.z = fmaf(M[8],  p.x, fmaf(M[9],  p.y, fmaf(M[10], p.z, fmaf(M[11], p.w, v.z))));
    r.w = fmaf(M[12], p.x, fmaf(M[13], p.y, fmaf(M[14], p.z, fmaf(M[15], p.w, v.w))));
    return r;
}

// ---- K1: per (b, chunk, d), 8-step zero-init recurrence -> end state (transposed) ----
__global__ __launch_bounds__(D_DIM)
void hippo_k1(const float* __restrict__ h, HippoConsts c) {
    __shared__ float sh[L_CH * D_DIM];   // 8KB chunk stage
    const int tid = threadIdx.x;
    const int j = blockIdx.x;
    const int b = blockIdx.y;

    // cooperative wide load: 2 independent LDG.128 per thread, issued up front
    const float4* src = (const float4*)(h + ((size_t)(b * T_LEN + j * L_CH)) * D_DIM);
    float4 v0 = __ldg(src + tid);
    float4 v1 = __ldg(src + D_DIM + tid);   // D_DIM float4 = 4 rows
    ((float4*)sh)[tid] = v0;
    ((float4*)sh)[D_DIM + tid] = v1;
    __syncthreads();

    float x0 = 0.f, x1 = 0.f, x2 = 0.f, x3 = 0.f;
    #pragma unroll
    for (int t = 0; t < L_CH; t++) {
        float hv = sh[t * D_DIM + tid];
        RSTEP(hv);
    }
    // transposed store: coalesced READS in KS (warp-contiguous j runs)
    g_eT[((size_t)b * D_DIM + tid) * NCHUNK + j] = make_float4(x0, x1, x2, x3);
}

// ---- KS: Kogge-Stone affine scan over 128 chunks -> exclusive start states ----
// Block covers all 128 chunks for 2 d-values: tid = dd*128 + j.
__global__ __launch_bounds__(256)
void hippo_ks(HippoConsts c) {
    __shared__ float4 s[256];
    const int tid = threadIdx.x;
    const int j   = tid & (NCHUNK - 1);
    const int dd  = tid >> 7;
    const int d   = blockIdx.x * 2 + dd;
    const int b   = blockIdx.y;

    // coalesced load from transposed layout: lanes = consecutive j
    float4 v = g_eT[((size_t)b * D_DIM + d) * NCHUNK + j];
    s[tid] = v;
    __syncthreads();

    #pragma unroll
    for (int r = 0; r < NROUND; r++) {
        const int off = 1 << r;
        float4 prev = make_float4(0.f, 0.f, 0.f, 0.f);
        const bool pred = (j >= off);
        if (pred) prev = s[tid - off];
        __syncthreads();
        if (pred) v = mvacc(c.Pk[r], prev, v);   // v += P^(2^r) * prev
        s[tid] = v;
        __syncthreads();
    }

    // exclusive prefix; store in [j][d] layout so K2 loads coalesce
    float4 st = make_float4(0.f, 0.f, 0.f, 0.f);
    if (j > 0) st = s[tid - 1];
    g_start[((size_t)b * NCHUNK + j) * D_DIM + d] = st;
}

// ---- K2: replay each chunk from its start state, writing all outputs ----
__global__ __launch_bounds__(D_DIM)
void hippo_k2(const float* __restrict__ h, float* __restrict__ out, HippoConsts c) {
    __shared__ float sh[L_CH * D_DIM];   // 8KB chunk stage
    const int tid = threadIdx.x;
    const int j = blockIdx.x;
    const int b = blockIdx.y;

    // issue start-state + h loads together (independent)
    float4 xs = g_start[((size_t)b * NCHUNK + j) * D_DIM + tid];
    const float4* src = (const float4*)(h + ((size_t)(b * T_LEN + j * L_CH)) * D_DIM);
    float4 v0 = __ldg(src + tid);
    float4 v1 = __ldg(src + D_DIM + tid);
    ((float4*)sh)[tid] = v0;
    ((float4*)sh)[D_DIM + tid] = v1;
    __syncthreads();

    float x0 = xs.x, x1 = xs.y, x2 = xs.z, x3 = xs.w;
    float* op = out + ((size_t)(b * T_LEN + j * L_CH)) * K_CH * D_DIM + tid;

    #pragma unroll
    for (int t = 0; t < L_CH; t++) {
        float hv = sh[t * D_DIM + tid];
        RSTEP(hv);
        op[0]         = x0;
        op[D_DIM]     = x1;
        op[2 * D_DIM] = x2;
        op[3 * D_DIM] = x3;
        op += (size_t)K_CH * D_DIM;
    }
}

// ---------------- host-side constant construction (double precision) ----------------

static void inv4x4(const double Min[4][4], double Mout[4][4]) {
    double a[4][8];
    for (int i = 0; i < 4; i++)
        for (int jj = 0; jj < 8; jj++)
            a[i][jj] = (jj < 4) ? Min[i][jj] : (jj - 4 == i ? 1.0 : 0.0);
    for (int col = 0; col < 4; col++) {
        int p = col;
        for (int rr = col + 1; rr < 4; rr++)
            if (fabs(a[rr][col]) > fabs(a[p][col])) p = rr;
        if (p != col)
            for (int jj = 0; jj < 8; jj++) { double t = a[col][jj]; a[col][jj] = a[p][jj]; a[p][jj] = t; }
        double piv = a[col][col];
        for (int jj = 0; jj < 8; jj++) a[col][jj] /= piv;
        for (int rr = 0; rr < 4; rr++) {
            if (rr == col) continue;
            double f = a[rr][col];
            for (int jj = 0; jj < 8; jj++) a[rr][jj] -= f * a[col][jj];
        }
    }
    for (int i = 0; i < 4; i++)
        for (int jj = 0; jj < 4; jj++)
            Mout[i][jj] = a[i][jj + 4];
}

static void matmul4(const double A[4][4], const double B[4][4], double C[4][4]) {
    for (int i = 0; i < 4; i++)
        for (int jj = 0; jj < 4; jj++) {
            double s = 0.0;
            for (int k = 0; k < 4; k++) s += A[i][k] * B[k][jj];
            C[i][jj] = s;
        }
}

extern "C" void kernel_launch(void* const* d_in, const int* in_sizes, int n_in,
                              void* d_out, int out_size) {
    const float* h;
    int sz0 = in_sizes[0], sz1 = in_sizes[1];
    if (sz0 > sz1) h = (const float*)d_in[0];
    else           h = (const float*)d_in[1];
    int hsz = (sz0 > sz1) ? sz0 : sz1;
    int B = hsz / (T_LEN * D_DIM);

    // --- HiPPO-LegT constants (matches reference _make_hippo_legt + bilinear) ---
    const double theta = 200.0;
    const double dt = 1.0 / theta;
    double A[4][4], Bv[4], Pn[4];
    for (int i = 0; i < 4; i++) Pn[i] = sqrt(2.0 * i + 1.0);
    for (int i = 0; i < 4; i++) {
        Bv[i] = Pn[i];
        for (int jj = 0; jj < 4; jj++) {
            double sg = 1.0;
            if (jj > i && ((jj - i) & 1)) sg = -1.0;   // (-1)^(j-i) upper triangle
            A[i][jj] = -Pn[i] * Pn[jj] * sg;
        }
    }
    double ImA[4][4], IpA[4][4], Inv[4][4], Abar[4][4];
    for (int i = 0; i < 4; i++)
        for (int jj = 0; jj < 4; jj++) {
            double eye = (i == jj) ? 1.0 : 0.0;
            ImA[i][jj] = eye - 0.5 * dt * A[i][jj];
            IpA[i][jj] = eye + 0.5 * dt * A[i][jj];
        }
    inv4x4(ImA, Inv);
    matmul4(Inv, IpA, Abar);
    double Bbar[4];
    for (int i = 0; i < 4; i++) {
        double sacc = 0.0;
        for (int jj = 0; jj < 4; jj++) sacc += Inv[i][jj] * Bv[jj] * dt;
        Bbar[i] = sacc;
    }

    // Pk[r] = Abar^(L_CH * 2^r)
    double Pw[NROUND][4][4], Tmp[4][4], Cur[4][4];
    for (int i = 0; i < 4; i++)
        for (int jj = 0; jj < 4; jj++) Cur[i][jj] = (i == jj) ? 1.0 : 0.0;
    for (int m = 0; m < L_CH; m++) {
        matmul4(Cur, Abar, Tmp);
        for (int i = 0; i < 4; i++)
            for (int jj = 0; jj < 4; jj++) Cur[i][jj] = Tmp[i][jj];
    }
    for (int i = 0; i < 4; i++)
        for (int jj = 0; jj < 4; jj++) Pw[0][i][jj] = Cur[i][jj];
    for (int r = 1; r < NROUND; r++) {
        matmul4(Pw[r - 1], Pw[r - 1], Tmp);
        for (int i = 0; i < 4; i++)
            for (int jj = 0; jj < 4; jj++) Pw[r][i][jj] = Tmp[i][jj];
    }

    HippoConsts c;
    for (int i = 0; i < 4; i++) {
        c.Bb[i] = (float)Bbar[i];
        for (int jj = 0; jj < 4; jj++)
            c.Ab[i * 4 + jj] = (float)Abar[i][jj];
    }
    for (int r = 0; r < NROUND; r++)
        for (int i = 0; i < 16; i++)
            c.Pk[r][i] = (float)Pw[r][i / 4][i % 4];

    dim3 gridC(NCHUNK, B);          // 128 x B
    dim3 gridS(D_DIM / 2, B);       // 128 x B
    hippo_k1<<<gridC, D_DIM>>>(h, c);
    hippo_ks<<<gridS, 256>>>(c);
    hippo_k2<<<gridC, D_DIM>>>(h, (float*)d_out, c);
}